// round 15
// baseline (speedup 1.0000x reference)
#include <cuda_runtime.h>
#include <cuda_bf16.h>

#define LL   128
#define BSZ  2
#define EE   768
#define HH   12
#define EH   384              // E/2
#define BHH  24               // B*H

// ---------------- fp32 scratch ----------------------------------------------
__device__ float g_nq[256 * EE];            // conv1d(query) output, (L,B,E)
__device__ float g_proj[256 * 4 * EH];      // [q | k | v | e] per row, (256,1536)
__device__ float g_dq[BHH * LL];
__device__ float g_dk[BHH * LL];
__device__ float g_de[LL * BHH];
__device__ float g_a[256 * EE];             // attention output in (L,B,E)
__device__ float g_y[256 * EE];             // deconv output

// ---------------- pre-split bf16 operand arrays (packed hi/lo words) ---------
__device__ unsigned g_qAh[196608],  g_qAl[196608];    // conv A  [256][768w]
__device__ unsigned g_aAh[196608],  g_aAl[196608];    // deconv A[256][768w]
__device__ unsigned g_nqh[98304],   g_nql[98304];     // proj A  [256][384w]
__device__ unsigned g_enth[98304],  g_entl[98304];    // proj A' [256][384w]
__device__ unsigned g_yh[98304],    g_yl[98304];      // out  A  [256][384w]
__device__ unsigned g_cWh[589824],  g_cWl[589824];    // conv W  [768][768w]
__device__ unsigned g_pWh[589824],  g_pWl[589824];    // proj W  [1536][384w]
__device__ unsigned g_dWh[589824],  g_dWl[589824];    // deconvW [768][768w]
__device__ unsigned g_oWh[294912],  g_oWl[294912];    // out  W  [768][384w]
__device__ float    g_projB[1536];

// ---------------- packed f32x2 helpers (attn kernel) -------------------------
#define FMA2(d, a, b) asm("fma.rn.f32x2 %0, %1, %2, %3;" \
                          : "=l"(d) : "l"(a), "l"(b), "l"(d))
#define PACK2(d, lo, hi) asm("mov.b64 %0, {%1, %2};" : "=l"(d) : "f"(lo), "f"(hi))
#define UNPK(lo, hi, s) asm("mov.b64 {%0, %1}, %2;" : "=f"(lo), "=f"(hi) : "l"(s))

// ---------------- bf16 mma.sync m16n8k16 ------------------------------------
__device__ __forceinline__ void mma16(float* d, const unsigned* a, const unsigned* b)
{
    asm volatile("mma.sync.aligned.m16n8k16.row.col.f32.bf16.bf16.f32 "
                 "{%0,%1,%2,%3}, {%4,%5,%6,%7}, {%8,%9}, {%0,%1,%2,%3};"
                 : "+f"(d[0]), "+f"(d[1]), "+f"(d[2]), "+f"(d[3])
                 : "r"(a[0]), "r"(a[1]), "r"(a[2]), "r"(a[3]),
                   "r"(b[0]), "r"(b[1]));
}

// truncating split: h = top-16 bits (PRMT), lo = bf16_rn(a - h)
__device__ __forceinline__ void bsplit(float2 v, unsigned& h, unsigned& l)
{
    const unsigned u0 = __float_as_uint(v.x);
    const unsigned u1 = __float_as_uint(v.y);
    h = __byte_perm(u0, u1, 0x7632);
    const float h0 = __uint_as_float(u0 & 0xffff0000u);
    const float h1 = __uint_as_float(u1 & 0xffff0000u);
    const float r0 = v.x - h0;
    const float r1 = v.y - h1;
    asm("cvt.rn.bf16x2.f32 %0, %1, %2;" : "=r"(l) : "f"(r1), "f"(r0));
}

// ---------------- init: zero atomic-accumulation targets ---------------------
__global__ __launch_bounds__(256)
void init_a_kernel()
{
    const int idx = blockIdx.x * 256 + threadIdx.x;   // 98304 float4
    float4 z = {0.f, 0.f, 0.f, 0.f};
    if (idx < 49152) ((float4*)g_nq)[idx] = z;
    else             ((float4*)g_y)[idx - 49152] = z;
}
__global__ __launch_bounds__(256)
void init_b_kernel(float* __restrict__ out)
{
    const int idx = blockIdx.x * 256 + threadIdx.x;   // 147456 float4
    float4 z = {0.f, 0.f, 0.f, 0.f};
    if (idx < 49152) ((float4*)out)[idx] = z;
    else             ((float4*)g_proj)[idx - 49152] = z;
}

// ---------------- convert kernels -------------------------------------------
__global__ __launch_bounds__(256)
void cvt_plain(const float* __restrict__ src, unsigned* __restrict__ dh,
               unsigned* __restrict__ dl, int nwords)
{
    const int i = blockIdx.x * 256 + threadIdx.x;
    if (i >= nwords) return;
    float2 v = *(const float2*)&src[2 * i];
    unsigned h, l; bsplit(v, h, l);
    dh[i] = h; dl[i] = l;
}

// [prev|cur] (PREV_FIRST=1, conv A) or [cur|prev] (=0, deconv A): 256x768 words
template<bool PREV_FIRST>
__global__ __launch_bounds__(256)
void cvt_shiftcat(const float* __restrict__ src, unsigned* __restrict__ dh,
                  unsigned* __restrict__ dl)
{
    const int i = blockIdx.x * 256 + threadIdx.x;     // 196608
    const int row = i / 768, w = i - row * 768;
    const int k = 2 * w;
    const bool first = k < EE;
    const int kk = first ? k : k - EE;
    const bool isprev = PREV_FIRST ? first : !first;
    float2 v;
    if (isprev) v = (row >= BSZ) ? *(const float2*)&src[(row - BSZ) * EE + kk]
                                 : make_float2(0.f, 0.f);
    else        v = *(const float2*)&src[row * EE + kk];
    unsigned h, l; bsplit(v, h, l);
    dh[i] = h; dl[i] = l;
}

__global__ __launch_bounds__(256)
void cvt_convw(const float* __restrict__ w, unsigned* __restrict__ dh,
               unsigned* __restrict__ dl)
{
    const int i = blockIdx.x * 256 + threadIdx.x;     // 589824
    const int o = i / 768, wd = i - o * 768;
    const int k = 2 * wd;
    const int kk = (k < EE) ? k : k - EE;
    const float4 f4 = *(const float4*)&w[(o * EE + kk) * 2];
    float2 v = (k < EE) ? make_float2(f4.x, f4.z) : make_float2(f4.y, f4.w);
    unsigned h, l; bsplit(v, h, l);
    dh[i] = h; dl[i] = l;
}

__global__ __launch_bounds__(256)
void cvt_projw(const float* __restrict__ W0, const float* __restrict__ W1,
               const float* __restrict__ W2, const float* __restrict__ W3,
               const float* __restrict__ b0, const float* __restrict__ b1,
               const float* __restrict__ b2, const float* __restrict__ b3,
               unsigned* __restrict__ dh, unsigned* __restrict__ dl)
{
    const int i = blockIdx.x * 256 + threadIdx.x;     // 589824
    const int o = i / 384, wd = i - o * 384;
    const int seg = o / EH, oo = o - seg * EH;
    const float* Wp = (seg == 0) ? W0 : (seg == 1) ? W1 : (seg == 2) ? W2 : W3;
    float2 v = *(const float2*)&Wp[oo * EE + 2 * wd];
    unsigned h, l; bsplit(v, h, l);
    dh[i] = h; dl[i] = l;
    if (i < 1536) {
        const int s2 = i / EH, o2 = i - s2 * EH;
        const float* bp = (s2 == 0) ? b0 : (s2 == 1) ? b1 : (s2 == 2) ? b2 : b3;
        g_projB[i] = bp[o2];
    }
}

__global__ __launch_bounds__(256)
void cvt_deconvw(const float* __restrict__ w, unsigned* __restrict__ dh,
                 unsigned* __restrict__ dl)
{
    __shared__ unsigned sh[32][33], sl[32][33];
    const int o0 = blockIdx.x * 32, w0 = blockIdx.y * 32;
    const int tid = threadIdx.x;
    const int oo = tid & 31, wi = tid >> 5;
    #pragma unroll
    for (int it = 0; it < 4; it++) {
        const int wd = w0 + wi + it * 8;
        const int k = 2 * wd;
        const int o = o0 + oo;
        float2 v;
        if (k < EE) {
            v.x = w[(k * EE + o) * 2];
            v.y = w[((k + 1) * EE + o) * 2];
        } else {
            v.x = w[((k - EE) * EE + o) * 2 + 1];
            v.y = w[((k + 1 - EE) * EE + o) * 2 + 1];
        }
        unsigned h, l; bsplit(v, h, l);
        sh[wi + it * 8][oo] = h; sl[wi + it * 8][oo] = l;
    }
    __syncthreads();
    const int w2 = tid & 31, oi = tid >> 5;
    #pragma unroll
    for (int it = 0; it < 4; it++) {
        const int o = o0 + oi + it * 8;
        dh[o * 768 + w0 + w2] = sh[w2][oi + it * 8];
        dl[o * 768 + w0 + w2] = sl[w2][oi + it * 8];
    }
}

// ---------------- unified tensor-core GEMM (pre-split bf16 operands) ---------
template<int N, int K, int KSPLIT, bool PSEL>
__global__ __launch_bounds__(128, 5)
void gemmT(const unsigned* __restrict__ Ah, const unsigned* __restrict__ Al,
           const unsigned* __restrict__ A2h, const unsigned* __restrict__ A2l,
           const unsigned* __restrict__ Bh, const unsigned* __restrict__ Bl,
           const float* __restrict__ bias, float* __restrict__ C)
{
    constexpr int BN = 64, BK = 32;
    constexpr int KW = K / 2;
    constexpr int NT = K / KSPLIT / BK;

    __shared__ __align__(16) unsigned AF[2][1024];
    __shared__ __align__(16) unsigned BF[2][2048];

    const int bn   = blockIdx.x * BN;
    const int bm   = blockIdx.y * 32;
    const int woff0 = blockIdx.z * (K / KSPLIT / 2);
    const int tid  = threadIdx.x;
    const int lane = tid & 31;
    const int wid  = tid >> 5;
    const int rh   = wid & 1;
    const int ch   = wid >> 1;
    const int grp  = lane >> 2;
    const int thr4 = lane & 3;
    const int cbB  = ch * 32;

    const int wIdx = tid & 15;
    const int fSub = tid >> 4;
    const int lK16 = wIdx >> 3;
    const int lHalf = (wIdx >> 2) & 1;
    const int lT4  = wIdx & 3;

    const unsigned* Aph = (PSEL && bn >= 3 * EH) ? A2h : Ah;
    const unsigned* Apl = (PSEL && bn >= 3 * EH) ? A2l : Al;

    unsigned arh[4], arl[4], brh[8], brl[8];

    auto loadA = [&](int t) {
        const int w = woff0 + t * 16 + wIdx;
        #pragma unroll
        for (int i = 0; i < 4; i++) {
            const int row = bm + i * 8 + fSub;
            arh[i] = Aph[row * KW + w];
            arl[i] = Apl[row * KW + w];
        }
    };
    auto loadB = [&](int t) {
        const int w = woff0 + t * 16 + wIdx;
        #pragma unroll
        for (int i = 0; i < 8; i++) {
            const int o = bn + i * 8 + fSub;
            brh[i] = Bh[o * KW + w];
            brl[i] = Bl[o * KW + w];
        }
    };
    auto storeTiles = [&](int nb) {
        uint2* A2s = (uint2*)AF[nb];
        #pragma unroll
        for (int i = 0; i < 4; i++) {
            const int r = i * 8 + fSub;
            const int q = (((r >> 4) * 2 + lK16) * 2 + lHalf) * 32 + (r & 7) * 4 + lT4;
            A2s[q * 2 + ((r >> 3) & 1)] = make_uint2(arh[i], arl[i]);
        }
        uint2* B2s = (uint2*)BF[nb];
        #pragma unroll
        for (int i = 0; i < 8; i++) {
            const int o = i * 8 + fSub;
            const int q = (((o >> 5) * 2 + lK16) * 4 + ((o >> 3) & 3)) * 32
                        + (o & 7) * 4 + lT4;
            B2s[q * 2 + lHalf] = make_uint2(brh[i], brl[i]);
        }
    };

    float dm[4][4] = {};
    float dc[4][4] = {};

    loadA(0); loadB(0);
    storeTiles(0);
    __syncthreads();

    int buf = 0;
    for (int t = 0; t < NT; t++) {
        if (t + 1 < NT) { loadA(t + 1); loadB(t + 1); }

        const uint4* AF4 = (const uint4*)AF[buf];
        const uint4* BF4 = (const uint4*)BF[buf];
        #pragma unroll
        for (int k16 = 0; k16 < 2; k16++) {
            const uint4 q0 = AF4[((rh * 2 + k16) * 2 + 0) * 32 + lane];
            const uint4 q1 = AF4[((rh * 2 + k16) * 2 + 1) * 32 + lane];
            const unsigned ah[4] = {q0.x, q0.z, q1.x, q1.z};
            const unsigned al[4] = {q0.y, q0.w, q1.y, q1.w};
            #pragma unroll
            for (int nt = 0; nt < 4; nt++) {
                const uint4 qb = BF4[((ch * 2 + k16) * 4 + nt) * 32 + lane];
                const unsigned bh[2] = {qb.x, qb.z};
                const unsigned bl[2] = {qb.y, qb.w};
                mma16(dm[nt], ah, bh);
                mma16(dc[nt], ah, bl);
                mma16(dc[nt], al, bh);
            }
        }

        if (t + 1 < NT) {
            storeTiles(buf ^ 1);
            __syncthreads();
            buf ^= 1;
        }
    }

    #pragma unroll
    for (int nt = 0; nt < 4; nt++) {
        const int col = bn + cbB + nt * 8 + 2 * thr4;
        float bias0 = bias[col], bias1 = bias[col + 1];
        if (blockIdx.z != 0) { bias0 = 0.f; bias1 = 0.f; }
        const int row = bm + rh * 16 + grp;
        atomicAdd(&C[row * N + col],           dm[nt][0] + dc[nt][0] + bias0);
        atomicAdd(&C[row * N + col + 1],       dm[nt][1] + dc[nt][1] + bias1);
        atomicAdd(&C[(row + 8) * N + col],     dm[nt][2] + dc[nt][2] + bias0);
        atomicAdd(&C[(row + 8) * N + col + 1], dm[nt][3] + dc[nt][3] + bias1);
    }
}

// ---------------- dq / dk / de precompute (9216 length-64 dots) -------------
__global__ __launch_bounds__(256)
void dots_kernel(const float* __restrict__ entity,
                 const float* __restrict__ attn_w)
{
    int w    = (blockIdx.x * blockDim.x + threadIdx.x) >> 5;
    int lane = threadIdx.x & 31;
    if (w >= 3 * BHH * LL) return;
    int which = w / (BHH * LL);
    int idx   = w % (BHH * LL);
    float v;
    if (which < 2) {
        int m = idx >> 7, x = idx & 127;
        int b = m / HH, h = m % HH;
        int row = x * BSZ + b;
        int base = (h < 6) ? (row * 1536 + which * EH + h * 64)
                           : (row * 1536 + 3 * EH + (h - 6) * 64);
        const float* wv = attn_w + which * 64;
        v = g_proj[base + lane] * wv[lane] + g_proj[base + lane + 32] * wv[lane + 32];
    } else {
        int i = idx / BHH, s = idx % BHH;
        int b = s / HH, h = s % HH;
        int base = (i * BSZ + b) * EE + h * 64;
        v = entity[base + lane] * attn_w[128 + lane]
          + entity[base + lane + 32] * attn_w[128 + lane + 32];
    }
    #pragma unroll
    for (int off = 16; off; off >>= 1) v += __shfl_down_sync(0xffffffffu, v, off);
    if (lane == 0) {
        if (which == 0)      g_dq[idx] = v;
        else if (which == 1) g_dk[idx] = v;
        else                 g_de[idx] = v;
    }
}

// ---------------- fused attention: 16 rows per block ------------------------
__global__ __launch_bounds__(256)
void attn_kernel(const float* __restrict__ attn_b)
{
    __shared__ float sT[3072];
    __shared__ float sqe[64];
    __shared__ __align__(8) float sp[16][128];

    const int ig  = blockIdx.x;
    const int bh  = blockIdx.y;
    const int tid = threadIdx.x;
    const int g0  = bh * 16384 + ig * 2048;
    const int i_src0 = g0 / 3072;

    for (int x = tid; x < 3072; x += 256) sT[x] = g_dk[x] - g_de[x];
    if (tid < 48) {
        const int il = tid / 24, s = tid - il * 24;
        const int isrc = min(i_src0 + il, LL - 1);
        sqe[tid] = g_dq[s * 128 + isrc] + g_de[isrc * 24 + s];
    }
    __syncthreads();
    const float bias = attn_b[0];

    const int lane = tid & 31, w = tid >> 5;
    #pragma unroll
    for (int rr = 0; rr < 2; rr++) {
        const int r  = w + rr * 8;
        const int gb = g0 + r * 128;
        float sc[4];
        #pragma unroll
        for (int q = 0; q < 4; q++) {
            const int g    = gb + q * 32 + lane;
            const int isrc = g / 3072;
            const int rem  = g - isrc * 3072;
            const int s    = rem % 24;
            float v = sqe[(isrc - i_src0) * 24 + s] + sT[rem] + bias;
            sc[q] = (v >= 0.f) ? v : 0.01f * v;
        }
        float m = fmaxf(fmaxf(sc[0], sc[1]), fmaxf(sc[2], sc[3]));
        #pragma unroll
        for (int off = 16; off; off >>= 1)
            m = fmaxf(m, __shfl_xor_sync(0xffffffffu, m, off));
        float e[4], sum = 0.f;
        #pragma unroll
        for (int q = 0; q < 4; q++) { e[q] = __expf(sc[q] - m); sum += e[q]; }
        #pragma unroll
        for (int off = 16; off; off >>= 1)
            sum += __shfl_xor_sync(0xffffffffu, sum, off);
        const float inv = 1.f / sum;
        #pragma unroll
        for (int q = 0; q < 4; q++) sp[r][q * 32 + lane] = e[q] * inv;
    }
    __syncthreads();

    const int b = bh / HH, h = bh - (bh / HH) * HH;
    const int off = (h < 6) ? (2 * EH + h * 64) : (3 * EH + (h - 6) * 64);
    const int d  = tid & 63;
    const int r0 = (tid >> 6) * 4;
    const float* Vp = g_proj + b * 1536 + off + d;

    unsigned long long acc2[4] = {};
    #pragma unroll 4
    for (int jj = 0; jj < 128; jj += 2) {
        const float v0 = Vp[jj * 3072];
        const float v1 = Vp[(jj + 1) * 3072];
        unsigned long long vv;
        PACK2(vv, v0, v1);
        #pragma unroll
        for (int r = 0; r < 4; r++) {
            const unsigned long long pp = *(const unsigned long long*)&sp[r0 + r][jj];
            FMA2(acc2[r], pp, vv);
        }
    }
    #pragma unroll
    for (int r = 0; r < 4; r++) {
        float lo, hi;
        UNPK(lo, hi, acc2[r]);
        const int i2 = ig * 16 + r0 + r;
        g_a[(i2 * BSZ + b) * EE + h * 64 + d] = lo + hi;
    }
}

// ---------------- launcher ---------------------------------------------------
extern "C" void kernel_launch(void* const* d_in, const int* in_sizes, int n_in,
                              void* d_out, int out_size)
{
    const float* query    = (const float*)d_in[0];
    const float* entity   = (const float*)d_in[1];
    const float* conv_w   = (const float*)d_in[2];
    const float* conv_b   = (const float*)d_in[3];
    const float* q_w      = (const float*)d_in[4];
    const float* q_b      = (const float*)d_in[5];
    const float* k_w      = (const float*)d_in[6];
    const float* k_b      = (const float*)d_in[7];
    const float* v_w      = (const float*)d_in[8];
    const float* v_b      = (const float*)d_in[9];
    const float* e_w      = (const float*)d_in[10];
    const float* e_b      = (const float*)d_in[11];
    const float* attn_w   = (const float*)d_in[12];
    const float* attn_b   = (const float*)d_in[13];
    const float* deconv_w = (const float*)d_in[14];
    const float* deconv_b = (const float*)d_in[15];
    const float* out_w    = (const float*)d_in[16];
    const float* out_b    = (const float*)d_in[17];
    float* out = (float*)d_out;

    unsigned *qAh, *qAl, *aAh, *aAl, *nqh, *nql, *enth, *entl, *yh, *yl;
    unsigned *cWh, *cWl, *pWh, *pWl, *dWh, *dWl, *oWh, *oWl;
    float *projB, *nqp, *yp, *ap, *projp;
    cudaGetSymbolAddress((void**)&qAh,  g_qAh);  cudaGetSymbolAddress((void**)&qAl,  g_qAl);
    cudaGetSymbolAddress((void**)&aAh,  g_aAh);  cudaGetSymbolAddress((void**)&aAl,  g_aAl);
    cudaGetSymbolAddress((void**)&nqh,  g_nqh);  cudaGetSymbolAddress((void**)&nql,  g_nql);
    cudaGetSymbolAddress((void**)&enth, g_enth); cudaGetSymbolAddress((void**)&entl, g_entl);
    cudaGetSymbolAddress((void**)&yh,   g_yh);   cudaGetSymbolAddress((void**)&yl,   g_yl);
    cudaGetSymbolAddress((void**)&cWh,  g_cWh);  cudaGetSymbolAddress((void**)&cWl,  g_cWl);
    cudaGetSymbolAddress((void**)&pWh,  g_pWh);  cudaGetSymbolAddress((void**)&pWl,  g_pWl);
    cudaGetSymbolAddress((void**)&dWh,  g_dWh);  cudaGetSymbolAddress((void**)&dWl,  g_dWl);
    cudaGetSymbolAddress((void**)&oWh,  g_oWh);  cudaGetSymbolAddress((void**)&oWl,  g_oWl);
    cudaGetSymbolAddress((void**)&projB, g_projB);
    cudaGetSymbolAddress((void**)&nqp,  g_nq);
    cudaGetSymbolAddress((void**)&yp,   g_y);
    cudaGetSymbolAddress((void**)&ap,   g_a);
    cudaGetSymbolAddress((void**)&projp, g_proj);

    init_a_kernel<<<384, 256>>>();
    init_b_kernel<<<576, 256>>>(out);
    cvt_shiftcat<true><<<768, 256>>>(query, qAh, qAl);
    cvt_plain<<<384, 256>>>(entity, enth, entl, 98304);
    cvt_convw<<<2304, 256>>>(conv_w, cWh, cWl);
    cvt_projw<<<2304, 256>>>(q_w, k_w, v_w, e_w, q_b, k_b, v_b, e_b, pWh, pWl);
    cvt_deconvw<<<dim3(24, 24), 256>>>(deconv_w, dWh, dWl);
    cvt_plain<<<1152, 256>>>(out_w, oWh, oWl, 294912);

    gemmT<768, 1536, 8, false><<<dim3(12, 8, 8), 128>>>(qAh, qAl, qAh, qAl,
                                                        cWh, cWl, conv_b, nqp);
    cvt_plain<<<384, 256>>>(nqp, nqh, nql, 98304);
    gemmT<1536, 768, 4, true><<<dim3(24, 8, 4), 128>>>(nqh, nql, enth, entl,
                                                       pWh, pWl, projB, projp);
    dots_kernel<<<1152, 256>>>(entity, attn_w);
    attn_kernel<<<dim3(8, BHH), 256>>>(attn_b);
    cvt_shiftcat<false><<<768, 256>>>(ap, aAh, aAl);
    gemmT<768, 1536, 8, false><<<dim3(12, 8, 8), 128>>>(aAh, aAl, aAh, aAl,
                                                        dWh, dWl, deconv_b, yp);
    cvt_plain<<<384, 256>>>(yp, yh, yl, 98304);
    gemmT<768, 768, 4, false><<<dim3(12, 8, 4), 128>>>(yh, yl, yh, yl,
                                                       oWh, oWl, out_b, out);
}

// round 16
// speedup vs baseline: 1.0606x; 1.0606x over previous
#include <cuda_runtime.h>
#include <cuda_bf16.h>

#define LL   128
#define BSZ  2
#define EE   768
#define HH   12
#define EH   384              // E/2
#define BHH  24               // B*H

// ---------------- fp32 scratch ----------------------------------------------
__device__ float g_nq[256 * EE];            // conv1d(query) output, (L,B,E)
__device__ float g_proj[256 * 4 * EH];      // [q | k | v | e] per row, (256,1536)
__device__ float g_dq[BHH * LL];
__device__ float g_dk[BHH * LL];
__device__ float g_de[LL * BHH];
__device__ float g_y[256 * EE];             // deconv output

// ---------------- pre-split bf16 operand arrays (packed hi/lo words) ---------
__device__ unsigned g_qAh[196608],  g_qAl[196608];    // conv A  [256][768w]
__device__ unsigned g_aAh[196608],  g_aAl[196608];    // deconv A[256][768w]
__device__ unsigned g_nqh[98304],   g_nql[98304];     // proj A  [256][384w]
__device__ unsigned g_enth[98304],  g_entl[98304];    // proj A' [256][384w]
__device__ unsigned g_yh[98304],    g_yl[98304];      // out  A  [256][384w]
__device__ unsigned g_cWh[589824],  g_cWl[589824];    // conv W  [768][768w]
__device__ unsigned g_pWh[589824],  g_pWl[589824];    // proj W  [1536][384w]
__device__ unsigned g_dWh[589824],  g_dWl[589824];    // deconvW [768][768w]
__device__ unsigned g_oWh[294912],  g_oWl[294912];    // out  W  [768][384w]
__device__ float    g_projB[1536];

// ---------------- packed f32x2 helpers (attn kernel) -------------------------
#define FMA2(d, a, b) asm("fma.rn.f32x2 %0, %1, %2, %3;" \
                          : "=l"(d) : "l"(a), "l"(b), "l"(d))
#define PACK2(d, lo, hi) asm("mov.b64 %0, {%1, %2};" : "=l"(d) : "f"(lo), "f"(hi))
#define UNPK(lo, hi, s) asm("mov.b64 {%0, %1}, %2;" : "=f"(lo), "=f"(hi) : "l"(s))

// ---------------- bf16 mma.sync m16n8k16 ------------------------------------
__device__ __forceinline__ void mma16(float* d, const unsigned* a, const unsigned* b)
{
    asm volatile("mma.sync.aligned.m16n8k16.row.col.f32.bf16.bf16.f32 "
                 "{%0,%1,%2,%3}, {%4,%5,%6,%7}, {%8,%9}, {%0,%1,%2,%3};"
                 : "+f"(d[0]), "+f"(d[1]), "+f"(d[2]), "+f"(d[3])
                 : "r"(a[0]), "r"(a[1]), "r"(a[2]), "r"(a[3]),
                   "r"(b[0]), "r"(b[1]));
}

// truncating split: h = top-16 bits (PRMT), lo = bf16_rn(a - h)
__device__ __forceinline__ void bsplit(float2 v, unsigned& h, unsigned& l)
{
    const unsigned u0 = __float_as_uint(v.x);
    const unsigned u1 = __float_as_uint(v.y);
    h = __byte_perm(u0, u1, 0x7632);
    const float h0 = __uint_as_float(u0 & 0xffff0000u);
    const float h1 = __uint_as_float(u1 & 0xffff0000u);
    const float r0 = v.x - h0;
    const float r1 = v.y - h1;
    asm("cvt.rn.bf16x2.f32 %0, %1, %2;" : "=r"(l) : "f"(r1), "f"(r0));
}

// ---------------- init kernels -----------------------------------------------
__global__ __launch_bounds__(256)
void init_a_kernel()
{
    const int idx = blockIdx.x * 256 + threadIdx.x;   // 98304 float4
    float4 z = {0.f, 0.f, 0.f, 0.f};
    if (idx < 49152) ((float4*)g_nq)[idx] = z;
    else             ((float4*)g_y)[idx - 49152] = z;
}
__global__ __launch_bounds__(256)
void init_b_kernel(float* __restrict__ out)
{
    const int idx = blockIdx.x * 256 + threadIdx.x;   // 147456 float4
    float4 z = {0.f, 0.f, 0.f, 0.f};
    if (idx < 49152) ((float4*)out)[idx] = z;
    else             ((float4*)g_proj)[idx - 49152] = z;
    // zero the [prev] half of aA rows 0..BSZ-1 (never written by attn)
    if (idx < 768) {
        const int row = idx / 384, t = idx - row * 384;
        g_aAh[row * 768 + 384 + t] = 0;
        g_aAl[row * 768 + 384 + t] = 0;
    }
}

// ---------------- mega convert: weights + static activations -----------------
// regions by blockIdx.x (8 words/thread, 2048 words/block):
//   [0,288)   convW 589824    [288,576) projW 589824 (+biases)
//   [576,720) outW  294912    [720,816) qA    196608
//   [816,864) ent   98304
__global__ __launch_bounds__(256)
void mega_cvt(const float* __restrict__ conv_w,
              const float* __restrict__ W0, const float* __restrict__ W1,
              const float* __restrict__ W2, const float* __restrict__ W3,
              const float* __restrict__ b0, const float* __restrict__ b1,
              const float* __restrict__ b2, const float* __restrict__ b3,
              const float* __restrict__ out_w,
              const float* __restrict__ query,
              const float* __restrict__ entity)
{
    const int b = blockIdx.x, tid = threadIdx.x;
    if (b < 288) {
        const int base = b * 2048;
        #pragma unroll
        for (int j = 0; j < 8; j++) {
            const int i = base + j * 256 + tid;
            const int o = i / 768, wd = i - o * 768;
            const int k = 2 * wd;
            const int kk = (k < EE) ? k : k - EE;
            const float4 f4 = *(const float4*)&conv_w[(o * EE + kk) * 2];
            float2 v = (k < EE) ? make_float2(f4.x, f4.z) : make_float2(f4.y, f4.w);
            unsigned h, l; bsplit(v, h, l);
            g_cWh[i] = h; g_cWl[i] = l;
        }
    } else if (b < 576) {
        const int base = (b - 288) * 2048;
        #pragma unroll
        for (int j = 0; j < 8; j++) {
            const int i = base + j * 256 + tid;
            const int o = i / 384, wd = i - o * 384;
            const int seg = o / EH, oo = o - seg * EH;
            const float* Wp = (seg == 0) ? W0 : (seg == 1) ? W1 : (seg == 2) ? W2 : W3;
            float2 v = *(const float2*)&Wp[oo * EE + 2 * wd];
            unsigned h, l; bsplit(v, h, l);
            g_pWh[i] = h; g_pWl[i] = l;
            if (i < 1536) {
                const int s2 = i / EH, o2 = i - s2 * EH;
                const float* bp = (s2 == 0) ? b0 : (s2 == 1) ? b1 : (s2 == 2) ? b2 : b3;
                g_projB[i] = bp[o2];
            }
        }
    } else if (b < 720) {
        const int base = (b - 576) * 2048;
        #pragma unroll
        for (int j = 0; j < 8; j++) {
            const int i = base + j * 256 + tid;
            const int o = i / 384, wd = i - o * 384;
            float2 v = *(const float2*)&out_w[o * EE + 2 * wd];
            unsigned h, l; bsplit(v, h, l);
            g_oWh[i] = h; g_oWl[i] = l;
        }
    } else if (b < 816) {
        const int base = (b - 720) * 2048;
        #pragma unroll
        for (int j = 0; j < 8; j++) {
            const int i = base + j * 256 + tid;
            const int row = i / 768, w = i - row * 768;
            const int k = 2 * w;
            const bool first = k < EE;                 // [prev | cur]
            const int kk = first ? k : k - EE;
            float2 v;
            if (first) v = (row >= BSZ) ? *(const float2*)&query[(row - BSZ) * EE + kk]
                                        : make_float2(0.f, 0.f);
            else       v = *(const float2*)&query[row * EE + kk];
            unsigned h, l; bsplit(v, h, l);
            g_qAh[i] = h; g_qAl[i] = l;
        }
    } else {
        const int base = (b - 816) * 2048;
        #pragma unroll
        for (int j = 0; j < 8; j++) {
            const int i = base + j * 256 + tid;
            float2 v = *(const float2*)&entity[2 * i];
            unsigned h, l; bsplit(v, h, l);
            g_enth[i] = h; g_entl[i] = l;
        }
    }
}

// deconv_w (k_in,o,2) -> [o][768w], tiled transpose
__global__ __launch_bounds__(256)
void cvt_deconvw(const float* __restrict__ w)
{
    __shared__ unsigned sh[32][33], sl[32][33];
    const int o0 = blockIdx.x * 32, w0 = blockIdx.y * 32;
    const int tid = threadIdx.x;
    const int oo = tid & 31, wi = tid >> 5;
    #pragma unroll
    for (int it = 0; it < 4; it++) {
        const int wd = w0 + wi + it * 8;
        const int k = 2 * wd;
        const int o = o0 + oo;
        float2 v;
        if (k < EE) {
            v.x = w[(k * EE + o) * 2];
            v.y = w[((k + 1) * EE + o) * 2];
        } else {
            v.x = w[((k - EE) * EE + o) * 2 + 1];
            v.y = w[((k + 1 - EE) * EE + o) * 2 + 1];
        }
        unsigned h, l; bsplit(v, h, l);
        sh[wi + it * 8][oo] = h; sl[wi + it * 8][oo] = l;
    }
    __syncthreads();
    const int w2 = tid & 31, oi = tid >> 5;
    #pragma unroll
    for (int it = 0; it < 4; it++) {
        const int o = o0 + oi + it * 8;
        g_dWh[o * 768 + w0 + w2] = sh[w2][oi + it * 8];
        g_dWl[o * 768 + w0 + w2] = sl[w2][oi + it * 8];
    }
}

// ILP-4 activation converts (96 blocks each)
__global__ __launch_bounds__(256)
void cvt_nq_kernel()
{
    const int i0 = blockIdx.x * 1024 + threadIdx.x;
    #pragma unroll
    for (int j = 0; j < 4; j++) {
        const int i = i0 + j * 256;
        float2 v = *(const float2*)&g_nq[2 * i];
        unsigned h, l; bsplit(v, h, l);
        g_nqh[i] = h; g_nql[i] = l;
    }
}
__global__ __launch_bounds__(256)
void cvt_y_kernel()
{
    const int i0 = blockIdx.x * 1024 + threadIdx.x;
    #pragma unroll
    for (int j = 0; j < 4; j++) {
        const int i = i0 + j * 256;
        float2 v = *(const float2*)&g_y[2 * i];
        unsigned h, l; bsplit(v, h, l);
        g_yh[i] = h; g_yl[i] = l;
    }
}

// ---------------- unified tensor-core GEMM (pre-split bf16 operands) ---------
template<int N, int K, int KSPLIT, bool PSEL>
__global__ __launch_bounds__(128, 5)
void gemmT(const unsigned* __restrict__ Ah, const unsigned* __restrict__ Al,
           const unsigned* __restrict__ A2h, const unsigned* __restrict__ A2l,
           const unsigned* __restrict__ Bh, const unsigned* __restrict__ Bl,
           const float* __restrict__ bias, float* __restrict__ C)
{
    constexpr int BN = 64, BK = 32;
    constexpr int KW = K / 2;
    constexpr int NT = K / KSPLIT / BK;

    __shared__ __align__(16) unsigned AF[2][1024];
    __shared__ __align__(16) unsigned BF[2][2048];

    const int bn   = blockIdx.x * BN;
    const int bm   = blockIdx.y * 32;
    const int woff0 = blockIdx.z * (K / KSPLIT / 2);
    const int tid  = threadIdx.x;
    const int lane = tid & 31;
    const int wid  = tid >> 5;
    const int rh   = wid & 1;
    const int ch   = wid >> 1;
    const int grp  = lane >> 2;
    const int thr4 = lane & 3;
    const int cbB  = ch * 32;

    const int wIdx = tid & 15;
    const int fSub = tid >> 4;
    const int lK16 = wIdx >> 3;
    const int lHalf = (wIdx >> 2) & 1;
    const int lT4  = wIdx & 3;

    const unsigned* Aph = (PSEL && bn >= 3 * EH) ? A2h : Ah;
    const unsigned* Apl = (PSEL && bn >= 3 * EH) ? A2l : Al;

    unsigned arh[4], arl[4], brh[8], brl[8];

    auto loadA = [&](int t) {
        const int w = woff0 + t * 16 + wIdx;
        #pragma unroll
        for (int i = 0; i < 4; i++) {
            const int row = bm + i * 8 + fSub;
            arh[i] = Aph[row * KW + w];
            arl[i] = Apl[row * KW + w];
        }
    };
    auto loadB = [&](int t) {
        const int w = woff0 + t * 16 + wIdx;
        #pragma unroll
        for (int i = 0; i < 8; i++) {
            const int o = bn + i * 8 + fSub;
            brh[i] = Bh[o * KW + w];
            brl[i] = Bl[o * KW + w];
        }
    };
    auto storeTiles = [&](int nb) {
        uint2* A2s = (uint2*)AF[nb];
        #pragma unroll
        for (int i = 0; i < 4; i++) {
            const int r = i * 8 + fSub;
            const int q = (((r >> 4) * 2 + lK16) * 2 + lHalf) * 32 + (r & 7) * 4 + lT4;
            A2s[q * 2 + ((r >> 3) & 1)] = make_uint2(arh[i], arl[i]);
        }
        uint2* B2s = (uint2*)BF[nb];
        #pragma unroll
        for (int i = 0; i < 8; i++) {
            const int o = i * 8 + fSub;
            const int q = (((o >> 5) * 2 + lK16) * 4 + ((o >> 3) & 3)) * 32
                        + (o & 7) * 4 + lT4;
            B2s[q * 2 + lHalf] = make_uint2(brh[i], brl[i]);
        }
    };

    float dm[4][4] = {};
    float dc[4][4] = {};

    loadA(0); loadB(0);
    storeTiles(0);
    __syncthreads();

    int buf = 0;
    for (int t = 0; t < NT; t++) {
        if (t + 1 < NT) { loadA(t + 1); loadB(t + 1); }

        const uint4* AF4 = (const uint4*)AF[buf];
        const uint4* BF4 = (const uint4*)BF[buf];
        #pragma unroll
        for (int k16 = 0; k16 < 2; k16++) {
            const uint4 q0 = AF4[((rh * 2 + k16) * 2 + 0) * 32 + lane];
            const uint4 q1 = AF4[((rh * 2 + k16) * 2 + 1) * 32 + lane];
            const unsigned ah[4] = {q0.x, q0.z, q1.x, q1.z};
            const unsigned al[4] = {q0.y, q0.w, q1.y, q1.w};
            #pragma unroll
            for (int nt = 0; nt < 4; nt++) {
                const uint4 qb = BF4[((ch * 2 + k16) * 4 + nt) * 32 + lane];
                const unsigned bh[2] = {qb.x, qb.z};
                const unsigned bl[2] = {qb.y, qb.w};
                mma16(dm[nt], ah, bh);
                mma16(dc[nt], ah, bl);
                mma16(dc[nt], al, bh);
            }
        }

        if (t + 1 < NT) {
            storeTiles(buf ^ 1);
            __syncthreads();
            buf ^= 1;
        }
    }

    #pragma unroll
    for (int nt = 0; nt < 4; nt++) {
        const int col = bn + cbB + nt * 8 + 2 * thr4;
        float bias0 = bias[col], bias1 = bias[col + 1];
        if (blockIdx.z != 0) { bias0 = 0.f; bias1 = 0.f; }
        const int row = bm + rh * 16 + grp;
        atomicAdd(&C[row * N + col],           dm[nt][0] + dc[nt][0] + bias0);
        atomicAdd(&C[row * N + col + 1],       dm[nt][1] + dc[nt][1] + bias1);
        atomicAdd(&C[(row + 8) * N + col],     dm[nt][2] + dc[nt][2] + bias0);
        atomicAdd(&C[(row + 8) * N + col + 1], dm[nt][3] + dc[nt][3] + bias1);
    }
}

// ---------------- dq / dk / de precompute (9216 length-64 dots) -------------
__global__ __launch_bounds__(256)
void dots_kernel(const float* __restrict__ entity,
                 const float* __restrict__ attn_w)
{
    int w    = (blockIdx.x * blockDim.x + threadIdx.x) >> 5;
    int lane = threadIdx.x & 31;
    if (w >= 3 * BHH * LL) return;
    int which = w / (BHH * LL);
    int idx   = w % (BHH * LL);
    float v;
    if (which < 2) {
        int m = idx >> 7, x = idx & 127;
        int b = m / HH, h = m % HH;
        int row = x * BSZ + b;
        int base = (h < 6) ? (row * 1536 + which * EH + h * 64)
                           : (row * 1536 + 3 * EH + (h - 6) * 64);
        const float* wv = attn_w + which * 64;
        v = g_proj[base + lane] * wv[lane] + g_proj[base + lane + 32] * wv[lane + 32];
    } else {
        int i = idx / BHH, s = idx % BHH;
        int b = s / HH, h = s % HH;
        int base = (i * BSZ + b) * EE + h * 64;
        v = entity[base + lane] * attn_w[128 + lane]
          + entity[base + lane + 32] * attn_w[128 + lane + 32];
    }
    #pragma unroll
    for (int off = 16; off; off >>= 1) v += __shfl_down_sync(0xffffffffu, v, off);
    if (lane == 0) {
        if (which == 0)      g_dq[idx] = v;
        else if (which == 1) g_dk[idx] = v;
        else                 g_de[idx] = v;
    }
}

// ---------------- fused attention: 16 rows per block -------------------------
// Epilogue writes the deconv-A bf16 split DIRECTLY ([cur|prev] layout).
__global__ __launch_bounds__(256)
void attn_kernel(const float* __restrict__ attn_b)
{
    __shared__ float sT[3072];
    __shared__ float sqe[64];
    __shared__ __align__(8) float sp[16][128];

    const int ig  = blockIdx.x;
    const int bh  = blockIdx.y;
    const int tid = threadIdx.x;
    const int g0  = bh * 16384 + ig * 2048;
    const int i_src0 = g0 / 3072;

    for (int x = tid; x < 3072; x += 256) sT[x] = g_dk[x] - g_de[x];
    if (tid < 48) {
        const int il = tid / 24, s = tid - il * 24;
        const int isrc = min(i_src0 + il, LL - 1);
        sqe[tid] = g_dq[s * 128 + isrc] + g_de[isrc * 24 + s];
    }
    __syncthreads();
    const float bias = attn_b[0];

    const int lane = tid & 31, w = tid >> 5;
    #pragma unroll
    for (int rr = 0; rr < 2; rr++) {
        const int r  = w + rr * 8;
        const int gb = g0 + r * 128;
        float sc[4];
        #pragma unroll
        for (int q = 0; q < 4; q++) {
            const int g    = gb + q * 32 + lane;
            const int isrc = g / 3072;
            const int rem  = g - isrc * 3072;
            const int s    = rem % 24;
            float v = sqe[(isrc - i_src0) * 24 + s] + sT[rem] + bias;
            sc[q] = (v >= 0.f) ? v : 0.01f * v;
        }
        float m = fmaxf(fmaxf(sc[0], sc[1]), fmaxf(sc[2], sc[3]));
        #pragma unroll
        for (int off = 16; off; off >>= 1)
            m = fmaxf(m, __shfl_xor_sync(0xffffffffu, m, off));
        float e[4], sum = 0.f;
        #pragma unroll
        for (int q = 0; q < 4; q++) { e[q] = __expf(sc[q] - m); sum += e[q]; }
        #pragma unroll
        for (int off = 16; off; off >>= 1)
            sum += __shfl_xor_sync(0xffffffffu, sum, off);
        const float inv = 1.f / sum;
        #pragma unroll
        for (int q = 0; q < 4; q++) sp[r][q * 32 + lane] = e[q] * inv;
    }
    __syncthreads();

    const int b = bh / HH, hh = bh - (bh / HH) * HH;
    const int off = (hh < 6) ? (2 * EH + hh * 64) : (3 * EH + (hh - 6) * 64);
    const int d  = tid & 63;
    const int r0 = (tid >> 6) * 4;
    const float* Vp = g_proj + b * 1536 + off + d;

    unsigned long long acc2[4] = {};
    #pragma unroll 4
    for (int jj = 0; jj < 128; jj += 2) {
        const float v0 = Vp[jj * 3072];
        const float v1 = Vp[(jj + 1) * 3072];
        unsigned long long vv;
        PACK2(vv, v0, v1);
        #pragma unroll
        for (int r = 0; r < 4; r++) {
            const unsigned long long pp = *(const unsigned long long*)&sp[r0 + r][jj];
            FMA2(acc2[r], pp, vv);
        }
    }
    const int word = hh * 32 + (d >> 1);          // col/2 for even d
    #pragma unroll
    for (int r = 0; r < 4; r++) {
        float lo, hi;
        UNPK(lo, hi, acc2[r]);
        const float total = lo + hi;
        const float nxt = __shfl_down_sync(0xffffffffu, total, 1);
        if ((d & 1) == 0) {
            unsigned h, l; bsplit(make_float2(total, nxt), h, l);
            const int i2 = ig * 16 + r0 + r;
            const int row = i2 * BSZ + b;
            g_aAh[row * 768 + word] = h;
            g_aAl[row * 768 + word] = l;
            const int row2 = row + BSZ;
            if (row2 < 256) {
                g_aAh[row2 * 768 + 384 + word] = h;
                g_aAl[row2 * 768 + 384 + word] = l;
            }
        }
    }
}

// ---------------- launcher ---------------------------------------------------
extern "C" void kernel_launch(void* const* d_in, const int* in_sizes, int n_in,
                              void* d_out, int out_size)
{
    const float* query    = (const float*)d_in[0];
    const float* entity   = (const float*)d_in[1];
    const float* conv_w   = (const float*)d_in[2];
    const float* conv_b   = (const float*)d_in[3];
    const float* q_w      = (const float*)d_in[4];
    const float* q_b      = (const float*)d_in[5];
    const float* k_w      = (const float*)d_in[6];
    const float* k_b      = (const float*)d_in[7];
    const float* v_w      = (const float*)d_in[8];
    const float* v_b      = (const float*)d_in[9];
    const float* e_w      = (const float*)d_in[10];
    const float* e_b      = (const float*)d_in[11];
    const float* attn_w   = (const float*)d_in[12];
    const float* attn_b   = (const float*)d_in[13];
    const float* deconv_w = (const float*)d_in[14];
    const float* deconv_b = (const float*)d_in[15];
    const float* out_w    = (const float*)d_in[16];
    const float* out_b    = (const float*)d_in[17];
    float* out = (float*)d_out;

    unsigned *qAh, *qAl, *aAh, *aAl, *nqh, *nql, *enth, *entl, *yh, *yl;
    unsigned *cWh, *cWl, *pWh, *pWl, *dWh, *dWl, *oWh, *oWl;
    float *projB, *nqp, *yp, *projp;
    cudaGetSymbolAddress((void**)&qAh,  g_qAh);  cudaGetSymbolAddress((void**)&qAl,  g_qAl);
    cudaGetSymbolAddress((void**)&aAh,  g_aAh);  cudaGetSymbolAddress((void**)&aAl,  g_aAl);
    cudaGetSymbolAddress((void**)&nqh,  g_nqh);  cudaGetSymbolAddress((void**)&nql,  g_nql);
    cudaGetSymbolAddress((void**)&enth, g_enth); cudaGetSymbolAddress((void**)&entl, g_entl);
    cudaGetSymbolAddress((void**)&yh,   g_yh);   cudaGetSymbolAddress((void**)&yl,   g_yl);
    cudaGetSymbolAddress((void**)&cWh,  g_cWh);  cudaGetSymbolAddress((void**)&cWl,  g_cWl);
    cudaGetSymbolAddress((void**)&pWh,  g_pWh);  cudaGetSymbolAddress((void**)&pWl,  g_pWl);
    cudaGetSymbolAddress((void**)&dWh,  g_dWh);  cudaGetSymbolAddress((void**)&dWl,  g_dWl);
    cudaGetSymbolAddress((void**)&oWh,  g_oWh);  cudaGetSymbolAddress((void**)&oWl,  g_oWl);
    cudaGetSymbolAddress((void**)&projB, g_projB);
    cudaGetSymbolAddress((void**)&nqp,  g_nq);
    cudaGetSymbolAddress((void**)&yp,   g_y);
    cudaGetSymbolAddress((void**)&projp, g_proj);

    init_a_kernel<<<384, 256>>>();                                // slot 0
    init_b_kernel<<<576, 256>>>(out);                             // slot 1
    mega_cvt<<<864, 256>>>(conv_w, q_w, k_w, v_w, e_w,
                           q_b, k_b, v_b, e_b, out_w,
                           query, entity);                        // slot 2
    gemmT<768, 1536, 8, false><<<dim3(12, 8, 8), 128>>>(qAh, qAl, qAh, qAl,
                                                        cWh, cWl, conv_b, nqp); // slot 3 (profiled)
    cvt_deconvw<<<dim3(24, 24), 256>>>(deconv_w);
    cvt_nq_kernel<<<96, 256>>>();
    gemmT<1536, 768, 4, true><<<dim3(24, 8, 4), 128>>>(nqh, nql, enth, entl,
                                                       pWh, pWl, projB, projp);
    dots_kernel<<<1152, 256>>>(entity, attn_w);
    attn_kernel<<<dim3(8, BHH), 256>>>(attn_b);
    gemmT<768, 1536, 8, false><<<dim3(12, 8, 8), 128>>>(aAh, aAl, aAh, aAl,
                                                        dWh, dWl, deconv_b, yp);
    cvt_y_kernel<<<96, 256>>>();
    gemmT<768, 768, 4, false><<<dim3(12, 8, 4), 128>>>(yh, yl, yh, yl,
                                                       oWh, oWl, out_b, out);
}

// round 17
// speedup vs baseline: 1.1341x; 1.0693x over previous
#include <cuda_runtime.h>
#include <cuda_bf16.h>

#define LL   128
#define BSZ  2
#define EE   768
#define HH   12
#define EH   384              // E/2
#define BHH  24               // B*H

// ---------------- fp32 scratch ----------------------------------------------
__device__ float g_nq[256 * EE];            // conv1d(query) output, (L,B,E)
__device__ float g_proj[256 * 4 * EH];      // [q | k | v | e] per row, (256,1536)
__device__ float g_dq[BHH * LL];
__device__ float g_dk[BHH * LL];
__device__ float g_de[LL * BHH];
__device__ float g_y[256 * EE];             // deconv output

// ---------------- pre-split bf16 operands: uint2 = {hi word, lo word} --------
__device__ uint2 g_qA[196608];              // conv A  [256][768w]
__device__ uint2 g_aA[196608];              // deconv A[256][768w]
__device__ uint2 g_nqS[98304];              // proj A  [256][384w]
__device__ uint2 g_entS[98304];             // proj A' [256][384w]
__device__ uint2 g_yS[98304];               // out  A  [256][384w]
__device__ uint2 g_cW[589824];              // conv W  [768][768w]
__device__ uint2 g_pW[589824];              // proj W  [1536][384w]
__device__ uint2 g_dW[589824];              // deconvW [768][768w]
__device__ uint2 g_oW[294912];              // out  W  [768][384w]
__device__ float g_projB[1536];

// ---------------- packed f32x2 helpers (attn kernel) -------------------------
#define FMA2(d, a, b) asm("fma.rn.f32x2 %0, %1, %2, %3;" \
                          : "=l"(d) : "l"(a), "l"(b), "l"(d))
#define PACK2(d, lo, hi) asm("mov.b64 %0, {%1, %2};" : "=l"(d) : "f"(lo), "f"(hi))
#define UNPK(lo, hi, s) asm("mov.b64 {%0, %1}, %2;" : "=f"(lo), "=f"(hi) : "l"(s))

// ---------------- bf16 mma.sync m16n8k16 ------------------------------------
__device__ __forceinline__ void mma16(float* d, const unsigned* a, const unsigned* b)
{
    asm volatile("mma.sync.aligned.m16n8k16.row.col.f32.bf16.bf16.f32 "
                 "{%0,%1,%2,%3}, {%4,%5,%6,%7}, {%8,%9}, {%0,%1,%2,%3};"
                 : "+f"(d[0]), "+f"(d[1]), "+f"(d[2]), "+f"(d[3])
                 : "r"(a[0]), "r"(a[1]), "r"(a[2]), "r"(a[3]),
                   "r"(b[0]), "r"(b[1]));
}

// truncating split: h = top-16 bits (PRMT), lo = bf16_rn(a - h)
__device__ __forceinline__ uint2 bsplit2(float2 v)
{
    const unsigned u0 = __float_as_uint(v.x);
    const unsigned u1 = __float_as_uint(v.y);
    uint2 r;
    r.x = __byte_perm(u0, u1, 0x7632);
    const float h0 = __uint_as_float(u0 & 0xffff0000u);
    const float h1 = __uint_as_float(u1 & 0xffff0000u);
    const float r0 = v.x - h0;
    const float r1 = v.y - h1;
    asm("cvt.rn.bf16x2.f32 %0, %1, %2;" : "=r"(r.y) : "f"(r1), "f"(r0));
    return r;
}

// ---------------- init kernels -----------------------------------------------
__global__ __launch_bounds__(256)
void init_a_kernel()
{
    const int idx = blockIdx.x * 256 + threadIdx.x;   // 98304 float4
    float4 z = {0.f, 0.f, 0.f, 0.f};
    if (idx < 49152) ((float4*)g_nq)[idx] = z;
    else             ((float4*)g_y)[idx - 49152] = z;
}
__global__ __launch_bounds__(256)
void init_b_kernel(float* __restrict__ out)
{
    const int idx = blockIdx.x * 256 + threadIdx.x;   // 147456 float4
    float4 z = {0.f, 0.f, 0.f, 0.f};
    if (idx < 49152) ((float4*)out)[idx] = z;
    else             ((float4*)g_proj)[idx - 49152] = z;
    // zero the [prev] half of aA rows 0..BSZ-1 (never written by attn)
    if (idx < 768) {
        const int row = idx / 384, t = idx - row * 384;
        g_aA[row * 768 + 384 + t] = make_uint2(0, 0);
    }
}

// ---------------- mega convert: weights + static activations -----------------
// regions by blockIdx.x (8 words/thread, 2048 words/block):
//   [0,288) convW   [288,576) projW(+biases)   [576,720) outW
//   [720,816) qA    [816,864) ent
__global__ __launch_bounds__(256)
void mega_cvt(const float* __restrict__ conv_w,
              const float* __restrict__ W0, const float* __restrict__ W1,
              const float* __restrict__ W2, const float* __restrict__ W3,
              const float* __restrict__ b0, const float* __restrict__ b1,
              const float* __restrict__ b2, const float* __restrict__ b3,
              const float* __restrict__ out_w,
              const float* __restrict__ query,
              const float* __restrict__ entity)
{
    const int b = blockIdx.x, tid = threadIdx.x;
    if (b < 288) {
        const int base = b * 2048;
        #pragma unroll
        for (int j = 0; j < 8; j++) {
            const int i = base + j * 256 + tid;
            const int o = i / 768, wd = i - o * 768;
            const int k = 2 * wd;
            const int kk = (k < EE) ? k : k - EE;
            const float4 f4 = *(const float4*)&conv_w[(o * EE + kk) * 2];
            float2 v = (k < EE) ? make_float2(f4.x, f4.z) : make_float2(f4.y, f4.w);
            g_cW[i] = bsplit2(v);
        }
    } else if (b < 576) {
        const int base = (b - 288) * 2048;
        #pragma unroll
        for (int j = 0; j < 8; j++) {
            const int i = base + j * 256 + tid;
            const int o = i / 384, wd = i - o * 384;
            const int seg = o / EH, oo = o - seg * EH;
            const float* Wp = (seg == 0) ? W0 : (seg == 1) ? W1 : (seg == 2) ? W2 : W3;
            float2 v = *(const float2*)&Wp[oo * EE + 2 * wd];
            g_pW[i] = bsplit2(v);
            if (i < 1536) {
                const int s2 = i / EH, o2 = i - s2 * EH;
                const float* bp = (s2 == 0) ? b0 : (s2 == 1) ? b1 : (s2 == 2) ? b2 : b3;
                g_projB[i] = bp[o2];
            }
        }
    } else if (b < 720) {
        const int base = (b - 576) * 2048;
        #pragma unroll
        for (int j = 0; j < 8; j++) {
            const int i = base + j * 256 + tid;
            const int o = i / 384, wd = i - o * 384;
            float2 v = *(const float2*)&out_w[o * EE + 2 * wd];
            g_oW[i] = bsplit2(v);
        }
    } else if (b < 816) {
        const int base = (b - 720) * 2048;
        #pragma unroll
        for (int j = 0; j < 8; j++) {
            const int i = base + j * 256 + tid;
            const int row = i / 768, w = i - row * 768;
            const int k = 2 * w;
            const bool first = k < EE;                 // [prev | cur]
            const int kk = first ? k : k - EE;
            float2 v;
            if (first) v = (row >= BSZ) ? *(const float2*)&query[(row - BSZ) * EE + kk]
                                        : make_float2(0.f, 0.f);
            else       v = *(const float2*)&query[row * EE + kk];
            g_qA[i] = bsplit2(v);
        }
    } else {
        const int base = (b - 816) * 2048;
        #pragma unroll
        for (int j = 0; j < 8; j++) {
            const int i = base + j * 256 + tid;
            float2 v = *(const float2*)&entity[2 * i];
            g_entS[i] = bsplit2(v);
        }
    }
}

// deconv_w (k_in,o,2) -> [o][768w], tiled transpose
__global__ __launch_bounds__(256)
void cvt_deconvw(const float* __restrict__ w)
{
    __shared__ uint2 sb[32][33];
    const int o0 = blockIdx.x * 32, w0 = blockIdx.y * 32;
    const int tid = threadIdx.x;
    const int oo = tid & 31, wi = tid >> 5;
    #pragma unroll
    for (int it = 0; it < 4; it++) {
        const int wd = w0 + wi + it * 8;
        const int k = 2 * wd;
        const int o = o0 + oo;
        float2 v;
        if (k < EE) {
            v.x = w[(k * EE + o) * 2];
            v.y = w[((k + 1) * EE + o) * 2];
        } else {
            v.x = w[((k - EE) * EE + o) * 2 + 1];
            v.y = w[((k + 1 - EE) * EE + o) * 2 + 1];
        }
        sb[wi + it * 8][oo] = bsplit2(v);
    }
    __syncthreads();
    const int w2 = tid & 31, oi = tid >> 5;
    #pragma unroll
    for (int it = 0; it < 4; it++) {
        const int o = o0 + oi + it * 8;
        g_dW[o * 768 + w0 + w2] = sb[w2][oi + it * 8];
    }
}

// ILP-4 activation converts (96 blocks each)
__global__ __launch_bounds__(256)
void cvt_nq_kernel()
{
    const int i0 = blockIdx.x * 1024 + threadIdx.x;
    #pragma unroll
    for (int j = 0; j < 4; j++) {
        const int i = i0 + j * 256;
        g_nqS[i] = bsplit2(*(const float2*)&g_nq[2 * i]);
    }
}
__global__ __launch_bounds__(256)
void cvt_y_kernel()
{
    const int i0 = blockIdx.x * 1024 + threadIdx.x;
    #pragma unroll
    for (int j = 0; j < 4; j++) {
        const int i = i0 + j * 256;
        g_yS[i] = bsplit2(*(const float2*)&g_y[2 * i]);
    }
}

// ---------------- unified tensor-core GEMM (interleaved bf16 operands) -------
template<int N, int K, int KSPLIT, bool PSEL>
__global__ __launch_bounds__(128, 5)
void gemmT(const uint2* __restrict__ A, const uint2* __restrict__ A2,
           const uint2* __restrict__ B,
           const float* __restrict__ bias, float* __restrict__ C)
{
    constexpr int BN = 64, BK = 32;
    constexpr int KW = K / 2;
    constexpr int NT = K / KSPLIT / BK;

    __shared__ __align__(16) unsigned AF[2][1024];
    __shared__ __align__(16) unsigned BF[2][2048];

    const int bn   = blockIdx.x * BN;
    const int bm   = blockIdx.y * 32;
    const int woff0 = blockIdx.z * (K / KSPLIT / 2);
    const int tid  = threadIdx.x;
    const int lane = tid & 31;
    const int wid  = tid >> 5;
    const int rh   = wid & 1;
    const int ch   = wid >> 1;
    const int grp  = lane >> 2;
    const int thr4 = lane & 3;
    const int cbB  = ch * 32;

    const int wIdx = tid & 15;
    const int fSub = tid >> 4;
    const int lK16 = wIdx >> 3;
    const int lHalf = (wIdx >> 2) & 1;
    const int lT4  = wIdx & 3;

    const uint2* Ap = (PSEL && bn >= 3 * EH) ? A2 : A;

    uint2 ar2[4], br2[8];

    auto loadA = [&](int t) {
        const int w = woff0 + t * 16 + wIdx;
        #pragma unroll
        for (int i = 0; i < 4; i++) {
            const int row = bm + i * 8 + fSub;
            ar2[i] = Ap[row * KW + w];
        }
    };
    auto loadB = [&](int t) {
        const int w = woff0 + t * 16 + wIdx;
        #pragma unroll
        for (int i = 0; i < 8; i++) {
            const int o = bn + i * 8 + fSub;
            br2[i] = B[o * KW + w];
        }
    };
    auto storeTiles = [&](int nb) {
        uint2* A2s = (uint2*)AF[nb];
        #pragma unroll
        for (int i = 0; i < 4; i++) {
            const int r = i * 8 + fSub;
            const int q = (((r >> 4) * 2 + lK16) * 2 + lHalf) * 32 + (r & 7) * 4 + lT4;
            A2s[q * 2 + ((r >> 3) & 1)] = ar2[i];
        }
        uint2* B2s = (uint2*)BF[nb];
        #pragma unroll
        for (int i = 0; i < 8; i++) {
            const int o = i * 8 + fSub;
            const int q = (((o >> 5) * 2 + lK16) * 4 + ((o >> 3) & 3)) * 32
                        + (o & 7) * 4 + lT4;
            B2s[q * 2 + lHalf] = br2[i];
        }
    };

    float dm[4][4] = {};
    float dc[4][4] = {};

    loadA(0); loadB(0);
    storeTiles(0);
    __syncthreads();

    int buf = 0;
    for (int t = 0; t < NT; t++) {
        if (t + 1 < NT) { loadA(t + 1); loadB(t + 1); }

        const uint4* AF4 = (const uint4*)AF[buf];
        const uint4* BF4 = (const uint4*)BF[buf];
        #pragma unroll
        for (int k16 = 0; k16 < 2; k16++) {
            const uint4 q0 = AF4[((rh * 2 + k16) * 2 + 0) * 32 + lane];
            const uint4 q1 = AF4[((rh * 2 + k16) * 2 + 1) * 32 + lane];
            const unsigned ah[4] = {q0.x, q0.z, q1.x, q1.z};
            const unsigned al[4] = {q0.y, q0.w, q1.y, q1.w};
            #pragma unroll
            for (int nt = 0; nt < 4; nt++) {
                const uint4 qb = BF4[((ch * 2 + k16) * 4 + nt) * 32 + lane];
                const unsigned bh[2] = {qb.x, qb.z};
                const unsigned bl[2] = {qb.y, qb.w};
                mma16(dm[nt], ah, bh);
                mma16(dc[nt], ah, bl);
                mma16(dc[nt], al, bh);
            }
        }

        if (t + 1 < NT) {
            storeTiles(buf ^ 1);
            __syncthreads();
            buf ^= 1;
        }
    }

    #pragma unroll
    for (int nt = 0; nt < 4; nt++) {
        const int col = bn + cbB + nt * 8 + 2 * thr4;
        float bias0 = bias[col], bias1 = bias[col + 1];
        if (blockIdx.z != 0) { bias0 = 0.f; bias1 = 0.f; }
        const int row = bm + rh * 16 + grp;
        atomicAdd(&C[row * N + col],           dm[nt][0] + dc[nt][0] + bias0);
        atomicAdd(&C[row * N + col + 1],       dm[nt][1] + dc[nt][1] + bias1);
        atomicAdd(&C[(row + 8) * N + col],     dm[nt][2] + dc[nt][2] + bias0);
        atomicAdd(&C[(row + 8) * N + col + 1], dm[nt][3] + dc[nt][3] + bias1);
    }
}

// ---------------- dq / dk / de precompute (9216 length-64 dots) -------------
__global__ __launch_bounds__(256)
void dots_kernel(const float* __restrict__ entity,
                 const float* __restrict__ attn_w)
{
    int w    = (blockIdx.x * blockDim.x + threadIdx.x) >> 5;
    int lane = threadIdx.x & 31;
    if (w >= 3 * BHH * LL) return;
    int which = w / (BHH * LL);
    int idx   = w % (BHH * LL);
    float v;
    if (which < 2) {
        int m = idx >> 7, x = idx & 127;
        int b = m / HH, h = m % HH;
        int row = x * BSZ + b;
        int base = (h < 6) ? (row * 1536 + which * EH + h * 64)
                           : (row * 1536 + 3 * EH + (h - 6) * 64);
        const float* wv = attn_w + which * 64;
        v = g_proj[base + lane] * wv[lane] + g_proj[base + lane + 32] * wv[lane + 32];
    } else {
        int i = idx / BHH, s = idx % BHH;
        int b = s / HH, h = s % HH;
        int base = (i * BSZ + b) * EE + h * 64;
        v = entity[base + lane] * attn_w[128 + lane]
          + entity[base + lane + 32] * attn_w[128 + lane + 32];
    }
    #pragma unroll
    for (int off = 16; off; off >>= 1) v += __shfl_down_sync(0xffffffffu, v, off);
    if (lane == 0) {
        if (which == 0)      g_dq[idx] = v;
        else if (which == 1) g_dk[idx] = v;
        else                 g_de[idx] = v;
    }
}

// ---------------- fused attention: 16 rows per block -------------------------
// Epilogue writes the deconv-A bf16 split DIRECTLY ([cur|prev] layout).
__global__ __launch_bounds__(256)
void attn_kernel(const float* __restrict__ attn_b)
{
    __shared__ float sT[3072];
    __shared__ float sqe[64];
    __shared__ __align__(8) float sp[16][128];

    const int ig  = blockIdx.x;
    const int bh  = blockIdx.y;
    const int tid = threadIdx.x;
    const int g0  = bh * 16384 + ig * 2048;
    const int i_src0 = g0 / 3072;

    for (int x = tid; x < 3072; x += 256) sT[x] = g_dk[x] - g_de[x];
    if (tid < 48) {
        const int il = tid / 24, s = tid - il * 24;
        const int isrc = min(i_src0 + il, LL - 1);
        sqe[tid] = g_dq[s * 128 + isrc] + g_de[isrc * 24 + s];
    }
    __syncthreads();
    const float bias = attn_b[0];

    const int lane = tid & 31, w = tid >> 5;
    #pragma unroll
    for (int rr = 0; rr < 2; rr++) {
        const int r  = w + rr * 8;
        const int gb = g0 + r * 128;
        float sc[4];
        #pragma unroll
        for (int q = 0; q < 4; q++) {
            const int g    = gb + q * 32 + lane;
            const int isrc = g / 3072;
            const int rem  = g - isrc * 3072;
            const int s    = rem % 24;
            float v = sqe[(isrc - i_src0) * 24 + s] + sT[rem] + bias;
            sc[q] = (v >= 0.f) ? v : 0.01f * v;
        }
        float m = fmaxf(fmaxf(sc[0], sc[1]), fmaxf(sc[2], sc[3]));
        #pragma unroll
        for (int off = 16; off; off >>= 1)
            m = fmaxf(m, __shfl_xor_sync(0xffffffffu, m, off));
        float e[4], sum = 0.f;
        #pragma unroll
        for (int q = 0; q < 4; q++) { e[q] = __expf(sc[q] - m); sum += e[q]; }
        #pragma unroll
        for (int off = 16; off; off >>= 1)
            sum += __shfl_xor_sync(0xffffffffu, sum, off);
        const float inv = 1.f / sum;
        #pragma unroll
        for (int q = 0; q < 4; q++) sp[r][q * 32 + lane] = e[q] * inv;
    }
    __syncthreads();

    const int b = bh / HH, hh = bh - (bh / HH) * HH;
    const int off = (hh < 6) ? (2 * EH + hh * 64) : (3 * EH + (hh - 6) * 64);
    const int d  = tid & 63;
    const int r0 = (tid >> 6) * 4;
    const float* Vp = g_proj + b * 1536 + off + d;

    unsigned long long acc2[4] = {};
    #pragma unroll 4
    for (int jj = 0; jj < 128; jj += 2) {
        const float v0 = Vp[jj * 3072];
        const float v1 = Vp[(jj + 1) * 3072];
        unsigned long long vv;
        PACK2(vv, v0, v1);
        #pragma unroll
        for (int r = 0; r < 4; r++) {
            const unsigned long long pp = *(const unsigned long long*)&sp[r0 + r][jj];
            FMA2(acc2[r], pp, vv);
        }
    }
    const int word = hh * 32 + (d >> 1);          // col/2 for even d
    #pragma unroll
    for (int r = 0; r < 4; r++) {
        float lo, hi;
        UNPK(lo, hi, acc2[r]);
        const float total = lo + hi;
        const float nxt = __shfl_down_sync(0xffffffffu, total, 1);
        if ((d & 1) == 0) {
            const uint2 hl = bsplit2(make_float2(total, nxt));
            const int i2 = ig * 16 + r0 + r;
            const int row = i2 * BSZ + b;
            g_aA[row * 768 + word] = hl;
            const int row2 = row + BSZ;
            if (row2 < 256) g_aA[row2 * 768 + 384 + word] = hl;
        }
    }
}

// ---------------- launcher ---------------------------------------------------
extern "C" void kernel_launch(void* const* d_in, const int* in_sizes, int n_in,
                              void* d_out, int out_size)
{
    const float* query    = (const float*)d_in[0];
    const float* entity   = (const float*)d_in[1];
    const float* conv_w   = (const float*)d_in[2];
    const float* conv_b   = (const float*)d_in[3];
    const float* q_w      = (const float*)d_in[4];
    const float* q_b      = (const float*)d_in[5];
    const float* k_w      = (const float*)d_in[6];
    const float* k_b      = (const float*)d_in[7];
    const float* v_w      = (const float*)d_in[8];
    const float* v_b      = (const float*)d_in[9];
    const float* e_w      = (const float*)d_in[10];
    const float* e_b      = (const float*)d_in[11];
    const float* attn_w   = (const float*)d_in[12];
    const float* attn_b   = (const float*)d_in[13];
    const float* deconv_w = (const float*)d_in[14];
    const float* deconv_b = (const float*)d_in[15];
    const float* out_w    = (const float*)d_in[16];
    const float* out_b    = (const float*)d_in[17];
    float* out = (float*)d_out;

    uint2 *qA, *aA, *nqS, *entS, *yS, *cW, *pW, *dW, *oW;
    float *projB, *nqp, *yp, *projp;
    cudaGetSymbolAddress((void**)&qA,   g_qA);
    cudaGetSymbolAddress((void**)&aA,   g_aA);
    cudaGetSymbolAddress((void**)&nqS,  g_nqS);
    cudaGetSymbolAddress((void**)&entS, g_entS);
    cudaGetSymbolAddress((void**)&yS,   g_yS);
    cudaGetSymbolAddress((void**)&cW,   g_cW);
    cudaGetSymbolAddress((void**)&pW,   g_pW);
    cudaGetSymbolAddress((void**)&dW,   g_dW);
    cudaGetSymbolAddress((void**)&oW,   g_oW);
    cudaGetSymbolAddress((void**)&projB, g_projB);
    cudaGetSymbolAddress((void**)&nqp,  g_nq);
    cudaGetSymbolAddress((void**)&yp,   g_y);
    cudaGetSymbolAddress((void**)&projp, g_proj);

    init_a_kernel<<<384, 256>>>();                                // slot 0
    init_b_kernel<<<576, 256>>>(out);                             // slot 1
    mega_cvt<<<864, 256>>>(conv_w, q_w, k_w, v_w, e_w,
                           q_b, k_b, v_b, e_b, out_w,
                           query, entity);                        // slot 2
    gemmT<768, 1536, 8, false><<<dim3(12, 8, 8), 128>>>(qA, qA, cW,
                                                        conv_b, nqp);  // slot 3 (profiled)
    cvt_deconvw<<<dim3(24, 24), 256>>>(deconv_w);
    cvt_nq_kernel<<<96, 256>>>();
    gemmT<1536, 768, 4, true><<<dim3(24, 8, 4), 128>>>(nqS, entS, pW,
                                                       projB, projp);
    dots_kernel<<<1152, 256>>>(entity, attn_w);
    attn_kernel<<<dim3(8, BHH), 256>>>(attn_b);
    gemmT<768, 1536, 8, false><<<dim3(12, 8, 8), 128>>>(aA, aA, dW,
                                                        deconv_b, yp);
    cvt_y_kernel<<<96, 256>>>();
    gemmT<768, 768, 4, false><<<dim3(12, 8, 4), 128>>>(yS, yS, oW,
                                                       out_b, out);
}